// round 5
// baseline (speedup 1.0000x reference)
#include <cuda_runtime.h>
#include <cuda_fp16.h>
#include <cstdint>

#define E_DIM   8192
#define N_NODES 2048
#define NCOL    512      // B*DH = 16*32
#define MT      64
#define NT      512
#define SPLITK  4
#define KSLICE  2048     // E_DIM / SPLITK
#define KC      32       // k per stage
#define NSTG    64       // KSLICE / KC

// ---- gemm smem (bytes) ----
#define RAW_ARR   9216           // 64 rows * 144B (padded fp32 rows)
#define RAW_SLOT  27648          // 3 arrays
#define B_OFF     82944          // 3 * RAW_SLOT
#define B_SLOT    32768          // 512 rows * 64B (pair-packed 128B lines)
#define AH_OFF    (B_OFF + 3*B_SLOT)      // 181248
#define AH_SLOT   4096           // 64 rows * 64B
#define GEMM_SMEM (AH_OFF + 3*AH_SLOT)    // 193536

// ---- xe smem (floats) ----
#define XE_TS_OFF 16384
#define XE_SMEM   ((16384 + 8*32*33) * 4)   // 99328 bytes

// scratch (__device__ globals; no allocation)
__device__ __align__(16) __half g_xeh[(size_t)NCOL * E_DIM];   // 8 MB  [c][e] fp16
__device__ float g_part[(size_t)SPLITK * N_NODES * NCOL];      // 16 MB

// ============================ helpers ============================
__device__ __forceinline__ uint32_t smem_u32(const void* p) {
    uint32_t a; asm("{ .reg .u64 t; cvta.to.shared.u64 t, %1; cvt.u32.u64 %0, t; }" : "=r"(a) : "l"(p));
    return a;
}
__device__ __forceinline__ void cpa16(uint32_t saddr, const void* g) {
    asm volatile("cp.async.cg.shared.global [%0], [%1], 16;" :: "r"(saddr), "l"(g));
}
#define CP_COMMIT() asm volatile("cp.async.commit_group;" ::: "memory")
#define CP_WAIT(n)  asm volatile("cp.async.wait_group %0;" :: "n"(n) : "memory")

__device__ __forceinline__ void ldmx4(uint32_t& r0, uint32_t& r1, uint32_t& r2, uint32_t& r3,
                                      uint32_t addr) {
    asm volatile("ldmatrix.sync.aligned.m8n8.x4.shared.b16 {%0,%1,%2,%3}, [%4];"
                 : "=r"(r0), "=r"(r1), "=r"(r2), "=r"(r3) : "r"(addr));
}
__device__ __forceinline__ void mma16816(float& d0, float& d1, float& d2, float& d3,
                                         uint32_t a0, uint32_t a1, uint32_t a2, uint32_t a3,
                                         uint32_t b0, uint32_t b1) {
    asm volatile("mma.sync.aligned.m16n8k16.row.col.f32.f16.f16.f32 "
                 "{%0,%1,%2,%3},{%4,%5,%6,%7},{%8,%9},{%0,%1,%2,%3};"
                 : "+f"(d0), "+f"(d1), "+f"(d2), "+f"(d3)
                 : "r"(a0), "r"(a1), "r"(a2), "r"(a3), "r"(b0), "r"(b1));
}
// fp16 tile addressing: 64B logical rows packed pairwise into 128B lines,
// 16B chunk c in 0..3; conflict-free for all ldmatrix phases and STS.128.
__device__ __forceinline__ uint32_t sw16(int row, int c) {
    return (uint32_t)(((row >> 1) * 128) + ((((row & 1) << 2) | (c ^ ((row >> 1) & 3))) * 16));
}

// ============================ kernel 1: xe ============================
// g_xeh[c=b*32+h][e] = fp16( relu( inputs[b,e,:] @ W[:,h] + bias[h] ) )
__global__ __launch_bounds__(256) void xe_kernel(const float* __restrict__ inp,
                                                 const float* __restrict__ W,
                                                 const float* __restrict__ bias) {
    extern __shared__ float xs[];
    float* in_s = xs;                                  // [256 rows][64]
    int t = threadIdx.x, lane = t & 31, warp = t >> 5;
    float* ts = xs + XE_TS_OFF + warp * (32 * 33);
    int eBase = blockIdx.x * 64;
    uint32_t in_sb = smem_u32(in_s);

    float Wr[64];
#pragma unroll
    for (int d = 0; d < 64; d++) Wr[d] = W[d * 32 + lane];
    float bl = bias[lane];

    int bb  = warp >> 1;
    int elo = (warp & 1) * 32;

    for (int bg = 0; bg < 4; bg++) {
#pragma unroll
        for (int j = 0; j < 16; j++) {
            int id = t + j * 256;
            int row = id >> 4, q = id & 15;
            const float* src = inp + ((size_t)(bg * 4 + (row >> 6)) * E_DIM + eBase + (row & 63)) * 64 + q * 4;
            cpa16(in_sb + (uint32_t)(row * 64 + q * 4) * 4u, src);
        }
        CP_COMMIT();
        CP_WAIT(0);
        __syncthreads();

#pragma unroll 1
        for (int rr = 0; rr < 32; rr++) {
            const float4* row = reinterpret_cast<const float4*>(in_s + (bb * 64 + elo + rr) * 64);
            float a0 = bl, a1 = 0.f, a2 = 0.f, a3 = 0.f;
#pragma unroll
            for (int dq = 0; dq < 16; dq++) {
                float4 iv = row[dq];               // uniform -> LDS.128 broadcast
                a0 = fmaf(iv.x, Wr[4 * dq + 0], a0);
                a1 = fmaf(iv.y, Wr[4 * dq + 1], a1);
                a2 = fmaf(iv.z, Wr[4 * dq + 2], a2);
                a3 = fmaf(iv.w, Wr[4 * dq + 3], a3);
            }
            ts[lane * 33 + rr] = fmaxf((a0 + a1) + (a2 + a3), 0.f);
        }
        __syncwarp();
#pragma unroll
        for (int j = 0; j < 32; j++) {
            g_xeh[((size_t)((bg * 4 + bb) * 32 + j)) * E_DIM + eBase + elo + lane] =
                __float2half_rn(ts[j * 33 + lane]);
        }
        __syncthreads();
    }
}

// ============================ kernel 2: fused A-build + fp16 GEMM ============================
// g_part[sk][m][c] = sum_{k in slice} fp16(w*inci+b)[m][k] * g_xeh[c][k]
// CTA 64x512, 512 threads. Warps 0-7: raw A cp.async + convert. Warps 8-15: B cp.async.
__global__ __launch_bounds__(512, 1) void gemm_fused(const float* __restrict__ wg,
                                                     const float* __restrict__ ig,
                                                     const float* __restrict__ bg) {
    extern __shared__ char sm[];
    uint32_t sb = smem_u32(sm);
    int t = threadIdx.x, lane = t & 31, warp = t >> 5;
    int wm = warp >> 3, wn = warp & 7;
    int mBase = blockIdx.x * MT;
    int sk = blockIdx.y;
    size_t kBase = (size_t)sk * KSLICE;

    // A-loader addressing (t < 256): owns (row=t>>2, 8 k-elems at c4*8)
    int arow = t >> 2, ac4 = t & 3;
    const float* gw = wg + (size_t)(mBase + arow) * E_DIM + kBase + ac4 * 8;
    const float* gi = ig + (size_t)(mBase + arow) * E_DIM + kBase + ac4 * 8;
    const float* gb = bg + (size_t)(mBase + arow) * E_DIM + kBase + ac4 * 8;
    uint32_t rawDst = sb + (uint32_t)(arow * 144 + ac4 * 32);
    uint32_t ahDst  = sb + AH_OFF + sw16(arow, ac4);

    // B-loader addressing (t >= 256): owns rows 2*tt, 2*tt+1 (one 128B line)
    int tt = t - 256;
    const __half* gB0 = g_xeh + (size_t)(2 * tt)     * E_DIM + kBase;
    const __half* gB1 = g_xeh + (size_t)(2 * tt + 1) * E_DIM + kBase;

    float acc[2][8][4];
#pragma unroll
    for (int mi = 0; mi < 2; mi++)
#pragma unroll
        for (int nj = 0; nj < 8; nj++)
#pragma unroll
            for (int v = 0; v < 4; v++) acc[mi][nj][v] = 0.f;

#define ISSUE_STAGE(s) do {                                                   \
    if (t < 256) {                                                            \
        uint32_t d = rawDst + (uint32_t)((s) % 3) * RAW_SLOT;                 \
        const float* pw = gw + (size_t)(s) * KC;                              \
        const float* pi = gi + (size_t)(s) * KC;                              \
        const float* pb = gb + (size_t)(s) * KC;                              \
        cpa16(d,                pw); cpa16(d + 16u,                pw + 4);   \
        cpa16(d + RAW_ARR,      pi); cpa16(d + RAW_ARR + 16u,      pi + 4);   \
        cpa16(d + 2u*RAW_ARR,   pb); cpa16(d + 2u*RAW_ARR + 16u,   pb + 4);   \
    } else {                                                                  \
        uint32_t bs = sb + B_OFF + (uint32_t)((s) % 3) * B_SLOT;              \
        _Pragma("unroll") for (int c = 0; c < 4; c++) {                       \
            cpa16(bs + sw16(2 * tt,     c), gB0 + (size_t)(s) * KC + c * 8);  \
            cpa16(bs + sw16(2 * tt + 1, c), gB1 + (size_t)(s) * KC + c * 8);  \
        }                                                                     \
    }                                                                         \
    CP_COMMIT();                                                              \
} while (0)

    ISSUE_STAGE(0);
    ISSUE_STAGE(1);

    for (int s = 0; s < NSTG; s++) {
        CP_WAIT(1);                            // own stage-s group complete
        if (t < 256) {
            // convert own raw chunk (visible: own cp.async retired)
            const char* rb = sm + (uint32_t)(s % 3) * RAW_SLOT + (arow * 144 + ac4 * 32);
            float4 w0 = *reinterpret_cast<const float4*>(rb);
            float4 w1 = *reinterpret_cast<const float4*>(rb + 16);
            float4 i0 = *reinterpret_cast<const float4*>(rb + RAW_ARR);
            float4 i1 = *reinterpret_cast<const float4*>(rb + RAW_ARR + 16);
            float4 b0 = *reinterpret_cast<const float4*>(rb + 2 * RAW_ARR);
            float4 b1 = *reinterpret_cast<const float4*>(rb + 2 * RAW_ARR + 16);
            __half2 h0 = __floats2half2_rn(fmaf(w0.x, i0.x, b0.x), fmaf(w0.y, i0.y, b0.y));
            __half2 h1 = __floats2half2_rn(fmaf(w0.z, i0.z, b0.z), fmaf(w0.w, i0.w, b0.w));
            __half2 h2 = __floats2half2_rn(fmaf(w1.x, i1.x, b1.x), fmaf(w1.y, i1.y, b1.y));
            __half2 h3 = __floats2half2_rn(fmaf(w1.z, i1.z, b1.z), fmaf(w1.w, i1.w, b1.w));
            uint4 o;
            o.x = *reinterpret_cast<uint32_t*>(&h0);
            o.y = *reinterpret_cast<uint32_t*>(&h1);
            o.z = *reinterpret_cast<uint32_t*>(&h2);
            o.w = *reinterpret_cast<uint32_t*>(&h3);
            *reinterpret_cast<uint4*>(sm + (ahDst - sb) + (uint32_t)(s % 3) * AH_SLOT) = o;
        }
        __syncthreads();                       // publish A(s) fp16 + B(s); frees slot (s+2)%3
        if (s + 2 < NSTG) ISSUE_STAGE(s + 2); else CP_COMMIT();

        uint32_t ah = sb + AH_OFF + (uint32_t)(s % 3) * AH_SLOT;
        uint32_t bh = sb + B_OFF  + (uint32_t)(s % 3) * B_SLOT;
#pragma unroll
        for (int kk = 0; kk < 2; kk++) {
            uint32_t a[2][4], b[8][2];
#pragma unroll
            for (int mi = 0; mi < 2; mi++) {
                int row_a = wm * 32 + mi * 16 + ((lane >> 3) & 1) * 8 + (lane & 7);
                int cA = kk * 2 + (lane >> 4);
                ldmx4(a[mi][0], a[mi][1], a[mi][2], a[mi][3], ah + sw16(row_a, cA));
            }
#pragma unroll
            for (int nj4 = 0; nj4 < 4; nj4++) {
                int row_b = wn * 64 + nj4 * 16 + (lane >> 4) * 8 + (lane & 7);
                int cB = kk * 2 + ((lane >> 3) & 1);
                ldmx4(b[2 * nj4][0], b[2 * nj4][1], b[2 * nj4 + 1][0], b[2 * nj4 + 1][1],
                      bh + sw16(row_b, cB));
            }
#pragma unroll
            for (int mi = 0; mi < 2; mi++)
#pragma unroll
                for (int nj = 0; nj < 8; nj++)
                    mma16816(acc[mi][nj][0], acc[mi][nj][1], acc[mi][nj][2], acc[mi][nj][3],
                             a[mi][0], a[mi][1], a[mi][2], a[mi][3],
                             b[nj][0], b[nj][1]);
        }
    }

    // epilogue: split-K partials
    int lr = lane >> 2, lq = lane & 3;
#pragma unroll
    for (int mi = 0; mi < 2; mi++)
#pragma unroll
        for (int nj = 0; nj < 8; nj++) {
            int m = mBase + wm * 32 + mi * 16 + lr;
            int c = wn * 64 + nj * 8 + 2 * lq;
            float* p = g_part + ((size_t)sk * N_NODES + m) * NCOL + c;
            *reinterpret_cast<float2*>(p) = make_float2(acc[mi][nj][0], acc[mi][nj][1]);
            *reinterpret_cast<float2*>(p + 8 * NCOL) = make_float2(acc[mi][nj][2], acc[mi][nj][3]);
        }
}

// ============================ kernel 3: reduce ============================
__global__ __launch_bounds__(256) void reduce_kernel(float* __restrict__ out) {
    int i = blockIdx.x * 256 + threadIdx.x;
    int pc = i * 4;
    int n = pc >> 9, c = pc & 511;
    float4 a = make_float4(0.f, 0.f, 0.f, 0.f);
#pragma unroll
    for (int s = 0; s < SPLITK; s++) {
        float4 v = *reinterpret_cast<const float4*>(g_part + ((size_t)s * N_NODES + n) * NCOL + c);
        a.x += v.x; a.y += v.y; a.z += v.z; a.w += v.w;
    }
    int b = c >> 5, h = c & 31;
    *reinterpret_cast<float4*>(out + ((size_t)b * N_NODES + n) * 32 + h) = a;
}

extern "C" void kernel_launch(void* const* d_in, const int* in_sizes, int n_in,
                              void* d_out, int out_size) {
    const float* inp  = (const float*)d_in[0];
    const float* W    = (const float*)d_in[1];
    const float* bias = (const float*)d_in[2];
    const float* inci = (const float*)d_in[3];
    const float* w    = (const float*)d_in[4];
    const float* b    = (const float*)d_in[5];
    float* out = (float*)d_out;

    cudaFuncSetAttribute(xe_kernel,  cudaFuncAttributeMaxDynamicSharedMemorySize, XE_SMEM);
    cudaFuncSetAttribute(gemm_fused, cudaFuncAttributeMaxDynamicSharedMemorySize, GEMM_SMEM);

    xe_kernel<<<E_DIM / 64, 256, XE_SMEM>>>(inp, W, bias);
    dim3 grid(N_NODES / MT, SPLITK);   // (32, 4) = 128 CTAs
    gemm_fused<<<grid, 512, GEMM_SMEM>>>(w, inci, b);
    reduce_kernel<<<(N_NODES * NCOL) / (4 * 256), 256>>>(out);
}